// round 3
// baseline (speedup 1.0000x reference)
#include <cuda_runtime.h>

// Problem constants (fixed shapes from reference)
#define TS    4096          // sequence length S
#define NH    16            // heads
#define HD    128           // head dim
#define NP    512           // prompt length P
#define NR    2             // regions
#define BM    64            // query tile
#define BN    64            // key chunk
#define BNP   68            // padded row for K^T in smem
#define PPAD  68            // padded row for P in smem
#define NT    256           // threads per CTA
#define KVSTRIDE (NH*HD)    // stride between consecutive keys in gmem (B=1)
#define SCALE 0.08838834764831845f  // 1/sqrt(128)

__device__ __forceinline__ float redmax16(float v) {
  v = fmaxf(v, __shfl_xor_sync(0xffffffffu, v, 1));
  v = fmaxf(v, __shfl_xor_sync(0xffffffffu, v, 2));
  v = fmaxf(v, __shfl_xor_sync(0xffffffffu, v, 4));
  v = fmaxf(v, __shfl_xor_sync(0xffffffffu, v, 8));
  return v;
}
__device__ __forceinline__ float redsum16(float v) {
  v += __shfl_xor_sync(0xffffffffu, v, 1);
  v += __shfl_xor_sync(0xffffffffu, v, 2);
  v += __shfl_xor_sync(0xffffffffu, v, 4);
  v += __shfl_xor_sync(0xffffffffu, v, 8);
  return v;
}

// Process one 64-key chunk against the 64-query tile with online softmax.
// act[qi] == 0  -> this chunk is fully masked for that query (contributes nothing).
__device__ __forceinline__ void process_chunk(
    const float* __restrict__ kc, const float* __restrict__ vc,
    const unsigned (&act)[4],
    float (&m)[4], float (&l)[4], float (&acc)[4][8],
    const float* __restrict__ sQ, float* __restrict__ sKt,
    float* __restrict__ sV, float* __restrict__ sP,
    int tid, int ty, int tx)
{
  const int q0 = ty * 4;
  const int k0 = tx * 4;
  const int dc = tx * 8;

  __syncthreads();   // previous chunk's consumers done with sKt/sV/sP

  // Load K (transposed) and V into smem. One warp covers exactly one key row
  // per iteration (32 float4 = 128 floats).
  #pragma unroll
  for (int i = 0; i < 8; i++) {
    int f  = tid + i * NT;        // float4 index over 64x128 tile
    int j  = f >> 5;              // key within chunk
    int d0 = (f & 31) << 2;       // dim
    float4 kk = *(const float4*)(kc + (size_t)j * KVSTRIDE + d0);
    sKt[(d0 + 0) * BNP + j] = kk.x;
    sKt[(d0 + 1) * BNP + j] = kk.y;
    sKt[(d0 + 2) * BNP + j] = kk.z;
    sKt[(d0 + 3) * BNP + j] = kk.w;
    *(float4*)&sV[j * HD + d0] = *(const float4*)(vc + (size_t)j * KVSTRIDE + d0);
  }
  __syncthreads();

  // Scores: 4 queries x 4 keys per thread, K=128
  float sc[4][4];
  #pragma unroll
  for (int a = 0; a < 4; a++)
    #pragma unroll
    for (int b = 0; b < 4; b++) sc[a][b] = 0.f;

  #pragma unroll 8
  for (int d0 = 0; d0 < HD; d0 += 4) {
    float4 qv[4], kv[4];
    #pragma unroll
    for (int qi = 0; qi < 4; qi++)
      qv[qi] = *(const float4*)&sQ[(q0 + qi) * HD + d0];
    #pragma unroll
    for (int dd = 0; dd < 4; dd++)
      kv[dd] = *(const float4*)&sKt[(d0 + dd) * BNP + k0];
    #pragma unroll
    for (int qi = 0; qi < 4; qi++) {
      const float* qf = (const float*)&qv[qi];
      #pragma unroll
      for (int dd = 0; dd < 4; dd++) {
        const float* kf = (const float*)&kv[dd];
        float qq = qf[dd];
        #pragma unroll
        for (int kj = 0; kj < 4; kj++)
          sc[qi][kj] = fmaf(qq, kf[kj], sc[qi][kj]);
      }
    }
  }

  // Online softmax update (per query; stats replicated across the 16 tx lanes)
  #pragma unroll
  for (int qi = 0; qi < 4; qi++) {
    bool a = (act[qi] != 0u);
    float rmax = fmaxf(fmaxf(sc[qi][0], sc[qi][1]), fmaxf(sc[qi][2], sc[qi][3]));
    rmax = redmax16(rmax);
    float mold = m[qi];
    float mnew = a ? fmaxf(mold, rmax) : mold;
    float corr = __expf(mold - mnew);   // ==1 if unchanged; ==0 on first active chunk (mold=-1e30)
    float ps = 0.f;
    #pragma unroll
    for (int kj = 0; kj < 4; kj++) {
      float p = a ? __expf(sc[qi][kj] - mnew) : 0.f;
      sc[qi][kj] = p;
      ps += p;
    }
    ps = redsum16(ps);
    l[qi] = l[qi] * corr + ps;
    m[qi] = mnew;
    #pragma unroll
    for (int dd = 0; dd < 8; dd++) acc[qi][dd] *= corr;
    *(float4*)&sP[(q0 + qi) * PPAD + k0] =
        make_float4(sc[qi][0], sc[qi][1], sc[qi][2], sc[qi][3]);
  }
  __syncthreads();

  // PV: acc[qi][0..7] += sum_j P[qi][j] * V[j][dc..dc+7]
  #pragma unroll 4
  for (int j = 0; j < BN; j++) {
    float4 v0 = *(const float4*)&sV[j * HD + dc];
    float4 v1 = *(const float4*)&sV[j * HD + dc + 4];
    #pragma unroll
    for (int qi = 0; qi < 4; qi++) {
      float p = sP[(q0 + qi) * PPAD + j];
      acc[qi][0] = fmaf(p, v0.x, acc[qi][0]);
      acc[qi][1] = fmaf(p, v0.y, acc[qi][1]);
      acc[qi][2] = fmaf(p, v0.z, acc[qi][2]);
      acc[qi][3] = fmaf(p, v0.w, acc[qi][3]);
      acc[qi][4] = fmaf(p, v1.x, acc[qi][4]);
      acc[qi][5] = fmaf(p, v1.y, acc[qi][5]);
      acc[qi][6] = fmaf(p, v1.z, acc[qi][6]);
      acc[qi][7] = fmaf(p, v1.w, acc[qi][7]);
    }
  }
}

__global__ __launch_bounds__(NT, 1)
void regional_attn_kernel(const float* __restrict__ q,
                          const float* __restrict__ k,
                          const float* __restrict__ v,
                          const float* __restrict__ rk,
                          const float* __restrict__ rv,
                          const int*  __restrict__ masks,
                          float* __restrict__ out)
{
  extern __shared__ float sm[];
  float* sQ  = sm;                     // [BM][HD]      8192 floats
  float* sKt = sQ + BM * HD;           // [HD][BNP]     8704
  float* sV  = sKt + HD * BNP;         // [BN][HD]      8192
  float* sP  = sV + BN * HD;           // [BM][PPAD]    4352

  const int tid = threadIdx.x;
  const int ty = tid >> 4;
  const int tx = tid & 15;
  const int q0 = ty * 4;
  const int dc = tx * 8;
  const int h = blockIdx.y;
  const int sBase = blockIdx.x * BM;

  // Load Q tile, pre-scaled by 1/sqrt(D)
  #pragma unroll
  for (int i = 0; i < 8; i++) {
    int f   = tid + i * NT;
    int row = f >> 5;
    int d0  = (f & 31) << 2;
    float4 qq = *(const float4*)(q + ((size_t)(sBase + row) * NH + h) * HD + d0);
    qq.x *= SCALE; qq.y *= SCALE; qq.z *= SCALE; qq.w *= SCALE;
    *(float4*)&sQ[row * HD + d0] = qq;
  }

  // Region membership bits for this thread's 4 queries
  unsigned act0[4], act1[4], actA[4];
  #pragma unroll
  for (int qi = 0; qi < 4; qi++) {
    int s = sBase + q0 + qi;
    act0[qi] = (unsigned)(masks[s] != 0);
    act1[qi] = (unsigned)(masks[TS + s] != 0);
    actA[qi] = 1u;
  }

  float mB[4], lB[4], mR[4], lR[4];
  float accB[4][8], accR[4][8];
  #pragma unroll
  for (int qi = 0; qi < 4; qi++) {
    mB[qi] = -1e30f; lB[qi] = 0.f;
    mR[qi] = -1e30f; lR[qi] = 0.f;
    #pragma unroll
    for (int dd = 0; dd < 8; dd++) { accB[qi][dd] = 0.f; accR[qi][dd] = 0.f; }
  }

  // Pass 1: base attention over k/v (always active)
  #pragma unroll 1
  for (int c = 0; c < NP / BN; c++) {
    const float* kc = k + ((size_t)(c * BN) * NH + h) * HD;
    const float* vc = v + ((size_t)(c * BN) * NH + h) * HD;
    process_chunk(kc, vc, actA, mB, lB, accB, sQ, sKt, sV, sP, tid, ty, tx);
  }

  // Pass 2: regional attention over the two regional blocks, per-query gated
  #pragma unroll 1
  for (int r = 0; r < NR; r++) {
    unsigned actR4[4];
    #pragma unroll
    for (int qi = 0; qi < 4; qi++) actR4[qi] = (r == 0) ? act0[qi] : act1[qi];
    #pragma unroll 1
    for (int c = 0; c < NP / BN; c++) {
      const float* kc = rk + ((size_t)(r * NP + c * BN) * NH + h) * HD;
      const float* vc = rv + ((size_t)(r * NP + c * BN) * NH + h) * HD;
      process_chunk(kc, vc, actR4, mR, lR, accR, sQ, sKt, sV, sP, tid, ty, tx);
    }
  }

  // Epilogue: out = 0.5*base + 0.5*(regional, falling back to base if no region)
  #pragma unroll
  for (int qi = 0; qi < 4; qi++) {
    int s = sBase + q0 + qi;
    float ib = 1.f / lB[qi];
    bool anyr = ((act0[qi] | act1[qi]) != 0u);
    float ir = anyr ? 1.f / lR[qi] : 0.f;
    float o[8];
    #pragma unroll
    for (int dd = 0; dd < 8; dd++) {
      float ob  = accB[qi][dd] * ib;
      float orr = anyr ? accR[qi][dd] * ir : ob;
      o[dd] = 0.5f * (ob + orr);
    }
    float4* dst = (float4*)(out + (size_t)s * (NH * HD) + h * HD + dc);
    dst[0] = make_float4(o[0], o[1], o[2], o[3]);
    dst[1] = make_float4(o[4], o[5], o[6], o[7]);
  }
}

extern "C" void kernel_launch(void* const* d_in, const int* in_sizes, int n_in,
                              void* d_out, int out_size)
{
  const float* q     = (const float*)d_in[0];
  const float* k     = (const float*)d_in[1];
  const float* v     = (const float*)d_in[2];
  const float* rk    = (const float*)d_in[3];
  const float* rv    = (const float*)d_in[4];
  const int*   masks = (const int*)d_in[5];
  float* out = (float*)d_out;

  const int smem = (BM * HD + HD * BNP + BN * HD + BM * PPAD) * (int)sizeof(float); // 117760
  cudaFuncSetAttribute(regional_attn_kernel,
                       cudaFuncAttributeMaxDynamicSharedMemorySize, smem);

  dim3 grid(TS / BM, NH);   // (64, 16) = 1024 CTAs
  regional_attn_kernel<<<grid, NT, smem>>>(q, k, v, rk, rv, masks, out);
}

// round 6
// speedup vs baseline: 1.1746x; 1.1746x over previous
#include <cuda_runtime.h>
#include <cstdint>

#define TS 4096
#define NH 16
#define HD 128
#define NP 512
#define BM 128            // queries per CTA
#define BN 64             // keys per chunk
#define NT 256            // 8 warps
#define NCHUNK 24         // 8 base + 2*8 regional
#define KVS (NH*HD)
#define SCALE 0.08838834764831845f

// smem float pitches chosen for conflict-free fragment LDS
#define QPITCH 132
#define KPITCH 132
#define VPITCH 136
#define QS_OFF 0u
#define KS_OFF 67584u          // 128*132*4
#define KS_BYTES 33792u        // 64*132*4
#define VS_OFF 135168u
#define VS_BYTES 34816u        // 64*136*4
#define SMEM_BYTES 204800u

static __device__ __forceinline__ void mma_tf32(float* d, const uint32_t* a, const uint32_t* b){
  asm volatile(
    "mma.sync.aligned.m16n8k8.row.col.f32.tf32.tf32.f32 "
    "{%0,%1,%2,%3}, {%4,%5,%6,%7}, {%8,%9}, {%0,%1,%2,%3};"
    : "+f"(d[0]), "+f"(d[1]), "+f"(d[2]), "+f"(d[3])
    : "r"(a[0]), "r"(a[1]), "r"(a[2]), "r"(a[3]), "r"(b[0]), "r"(b[1]));
}
static __device__ __forceinline__ uint32_t f2tf(float x){
  uint32_t y; asm("cvt.rna.tf32.f32 %0, %1;" : "=r"(y) : "f"(x)); return y;
}
// hi/lo split for 3xTF32 compensation
static __device__ __forceinline__ void tfsplit(float x, uint32_t& hi, uint32_t& lo){
  hi = f2tf(x);
  lo = f2tf(x - __uint_as_float(hi));
}
static __device__ __forceinline__ void cpa16(uint32_t dst, const float* src){
  asm volatile("cp.async.cg.shared.global [%0], [%1], 16;" :: "r"(dst), "l"(src) : "memory");
}
#define CP_COMMIT() asm volatile("cp.async.commit_group;" ::: "memory")
#define CP_WAIT0()  asm volatile("cp.async.wait_group 0;" ::: "memory")

static __device__ __forceinline__ uint32_t s2u(const void* p){
  uint32_t a; asm("{ .reg .u64 t; cvta.to.shared.u64 t, %1; cvt.u32.u64 %0, t; }" : "=r"(a) : "l"(p)); return a;
}

// gmem base pointer for chunk t (0-7: base block; 8-23: regional blocks)
static __device__ __forceinline__ const float* cbase(const float* base, const float* reg, int t, int h){
  if (t < 8) return base + ((size_t)(t*BN)*NH + h)*(size_t)HD;
  int u = t - 8; int rg = u >> 3; int c = u & 7;
  return reg + ((size_t)(rg*NP + c*BN)*NH + h)*(size_t)HD;
}

static __device__ __forceinline__ void load_chunk(uint32_t sb, const float* kc, const float* vc,
                                                  int buf, int tid){
  uint32_t kdst = sb + KS_OFF + (uint32_t)buf * KS_BYTES;
  uint32_t vdst = sb + VS_OFF + (uint32_t)buf * VS_BYTES;
  #pragma unroll
  for (int i = 0; i < 8; i++){
    int f = i*NT + tid; int j = f >> 5; int d0 = (f & 31) << 2;
    cpa16(kdst + (uint32_t)(j*KPITCH + d0)*4u, kc + (size_t)j*KVS + d0);
    cpa16(vdst + (uint32_t)(j*VPITCH + d0)*4u, vc + (size_t)j*KVS + d0);
  }
}

__global__ __launch_bounds__(NT, 1)
void regional_attn_hmma(const float* __restrict__ q, const float* __restrict__ k,
                        const float* __restrict__ v, const float* __restrict__ rk,
                        const float* __restrict__ rv, const int* __restrict__ masks,
                        float* __restrict__ out)
{
  extern __shared__ float smf[];
  const uint32_t sb = s2u(smf);
  const int tid  = threadIdx.x;
  const int lane = tid & 31;
  const int wid  = tid >> 5;
  const int quad = lane >> 2;     // 0..7
  const int qt   = lane & 3;      // 0..3
  const int h = blockIdx.y;
  const int sBase = blockIdx.x * BM;

  // Q tile -> smem (cp.async), 128x128 f32, pitch 132
  #pragma unroll
  for (int i = 0; i < 16; i++){
    int f = i*NT + tid; int r = f >> 5; int d0 = (f & 31) << 2;
    cpa16(sb + QS_OFF + (uint32_t)(r*QPITCH + d0)*4u,
          q + ((size_t)(sBase + r)*NH + h)*(size_t)HD + d0);
  }
  load_chunk(sb, cbase(k, rk, 0, h), cbase(v, rv, 0, h), 0, tid);
  CP_COMMIT();

  // region membership for this thread's two rows
  const int s0 = sBase + wid*16 + quad;      // row0 (global)
  const int s1 = s0 + 8;                     // row1
  const int m0r0 = (masks[s0]      != 0), m0r1 = (masks[s1]      != 0);
  const int m1r0 = (masks[TS + s0] != 0), m1r1 = (masks[TS + s1] != 0);

  float oB[16][4], oR[16][4];
  #pragma unroll
  for (int n = 0; n < 16; n++)
    #pragma unroll
    for (int e = 0; e < 4; e++){ oB[n][e] = 0.f; oR[n][e] = 0.f; }
  float lB0 = 0.f, lB1 = 0.f, lR0 = 0.f, lR1 = 0.f;

  const float* Qa = smf + QS_OFF/4 + (wid*16 + quad)*QPITCH + qt;

  for (int t = 0; t < NCHUNK; t++){
    CP_WAIT0();
    __syncthreads();                       // chunk t visible; all warps done with t-1 buffers

    if (t + 1 < NCHUNK){
      load_chunk(sb, cbase(k, rk, t+1, h), cbase(v, rv, t+1, h), (t+1)&1, tid);
      CP_COMMIT();
    }

    const float* Kc = smf + KS_OFF/4 + (t&1)*(KS_BYTES/4);
    const float* Vc = smf + VS_OFF/4 + (t&1)*(VS_BYTES/4);

    // ---- QK^T with 3xTF32 compensation:
    //      S ~= Qhi*Khi + Qhi*Klo + Qlo*Khi   (lo*lo dropped, ~1e-7)
    float sf[8][4];
    #pragma unroll
    for (int n = 0; n < 8; n++)
      #pragma unroll
      for (int e = 0; e < 4; e++) sf[n][e] = 0.f;

    const float* Kb = Kc + quad*KPITCH + qt;
    #pragma unroll
    for (int k0 = 0; k0 < 16; k0++){
      uint32_t ahi[4], alo[4];
      tfsplit(Qa[k0*8],                ahi[0], alo[0]);
      tfsplit(Qa[8*QPITCH + k0*8],     ahi[1], alo[1]);
      tfsplit(Qa[k0*8 + 4],            ahi[2], alo[2]);
      tfsplit(Qa[8*QPITCH + k0*8 + 4], ahi[3], alo[3]);
      #pragma unroll
      for (int n = 0; n < 8; n++){
        uint32_t bhi[2], blo[2];
        tfsplit(Kb[n*8*KPITCH + k0*8],     bhi[0], blo[0]);
        tfsplit(Kb[n*8*KPITCH + k0*8 + 4], bhi[1], blo[1]);
        mma_tf32(sf[n], ahi, bhi);
        mma_tf32(sf[n], ahi, blo);
        mma_tf32(sf[n], alo, bhi);
      }
    }

    // ---- softmax numerators (no max-shift; masked rows -> exact 0)
    const int a0 = (t < 8) ? 1 : ((t < 16) ? m0r0 : m1r0);
    const int a1 = (t < 8) ? 1 : ((t < 16) ? m0r1 : m1r1);
    float su0 = 0.f, su1 = 0.f;
    #pragma unroll
    for (int n = 0; n < 8; n++){
      float p0 = a0 ? __expf(sf[n][0]*SCALE) : 0.f;
      float p1 = a0 ? __expf(sf[n][1]*SCALE) : 0.f;
      float p2 = a1 ? __expf(sf[n][2]*SCALE) : 0.f;
      float p3 = a1 ? __expf(sf[n][3]*SCALE) : 0.f;
      sf[n][0] = p0; sf[n][1] = p1; sf[n][2] = p2; sf[n][3] = p3;
      su0 += p0 + p1; su1 += p2 + p3;
    }
    if (t < 8){ lB0 += su0; lB1 += su1; } else { lR0 += su0; lR1 += su1; }

    // ---- P @ V: O += P(16x64) @ V(64x128); A-frags built from sf via quad-shuffles
    float (*o)[4] = (t < 8) ? oB : oR;
    const float* Vb = Vc + qt*VPITCH + quad;
    #pragma unroll
    for (int k0 = 0; k0 < 8; k0++){
      const unsigned FULL = 0xffffffffu;
      int i0 = qt >> 1, i1 = i0 + 2;
      float x0 = __shfl_sync(FULL, sf[k0][0], i0, 4);
      float x1 = __shfl_sync(FULL, sf[k0][1], i0, 4);
      float y0 = __shfl_sync(FULL, sf[k0][2], i0, 4);
      float y1 = __shfl_sync(FULL, sf[k0][3], i0, 4);
      float z0 = __shfl_sync(FULL, sf[k0][0], i1, 4);
      float z1 = __shfl_sync(FULL, sf[k0][1], i1, 4);
      float w0 = __shfl_sync(FULL, sf[k0][2], i1, 4);
      float w1 = __shfl_sync(FULL, sf[k0][3], i1, 4);
      uint32_t pa[4];
      pa[0] = f2tf((qt & 1) ? x1 : x0);
      pa[1] = f2tf((qt & 1) ? y1 : y0);
      pa[2] = f2tf((qt & 1) ? z1 : z0);
      pa[3] = f2tf((qt & 1) ? w1 : w0);
      #pragma unroll
      for (int n = 0; n < 16; n++){
        uint32_t b[2];
        b[0] = __float_as_uint(Vb[k0*8*VPITCH + n*8]);
        b[1] = __float_as_uint(Vb[(k0*8 + 4)*VPITCH + n*8]);
        mma_tf32(o[n], pa, b);
      }
    }
  }

  // ---- epilogue: quad-reduce sums, normalize, blend, store
  const unsigned FULL = 0xffffffffu;
  lB0 += __shfl_xor_sync(FULL, lB0, 1, 4); lB0 += __shfl_xor_sync(FULL, lB0, 2, 4);
  lB1 += __shfl_xor_sync(FULL, lB1, 1, 4); lB1 += __shfl_xor_sync(FULL, lB1, 2, 4);
  lR0 += __shfl_xor_sync(FULL, lR0, 1, 4); lR0 += __shfl_xor_sync(FULL, lR0, 2, 4);
  lR1 += __shfl_xor_sync(FULL, lR1, 1, 4); lR1 += __shfl_xor_sync(FULL, lR1, 2, 4);

  const int anyr0 = m0r0 | m1r0;
  const int anyr1 = m0r1 | m1r1;
  const float ib0 = 1.f / lB0, ib1 = 1.f / lB1;
  const float ir0 = anyr0 ? 1.f / lR0 : 0.f;
  const float ir1 = anyr1 ? 1.f / lR1 : 0.f;

  float* o0p = out + (size_t)s0*(size_t)(NH*HD) + (size_t)h*HD + 2*qt;
  float* o1p = out + (size_t)s1*(size_t)(NH*HD) + (size_t)h*HD + 2*qt;
  #pragma unroll
  for (int n = 0; n < 16; n++){
    float b0 = oB[n][0]*ib0, b1 = oB[n][1]*ib0;
    float b2 = oB[n][2]*ib1, b3 = oB[n][3]*ib1;
    float r0 = anyr0 ? oR[n][0]*ir0 : b0;
    float r1 = anyr0 ? oR[n][1]*ir0 : b1;
    float r2 = anyr1 ? oR[n][2]*ir1 : b2;
    float r3 = anyr1 ? oR[n][3]*ir1 : b3;
    *(float2*)(o0p + n*8) = make_float2(0.5f*(b0+r0), 0.5f*(b1+r1));
    *(float2*)(o1p + n*8) = make_float2(0.5f*(b2+r2), 0.5f*(b3+r3));
  }
}

extern "C" void kernel_launch(void* const* d_in, const int* in_sizes, int n_in,
                              void* d_out, int out_size)
{
  const float* q     = (const float*)d_in[0];
  const float* k     = (const float*)d_in[1];
  const float* v     = (const float*)d_in[2];
  const float* rk    = (const float*)d_in[3];
  const float* rv    = (const float*)d_in[4];
  const int*   masks = (const int*)d_in[5];
  float* out = (float*)d_out;

  cudaFuncSetAttribute(regional_attn_hmma,
                       cudaFuncAttributeMaxDynamicSharedMemorySize, SMEM_BYTES);
  dim3 grid(TS / BM, NH);   // (32, 16) = 512 CTAs
  regional_attn_hmma<<<grid, NT, SMEM_BYTES>>>(q, k, v, rk, rv, masks, out);
}

// round 7
// speedup vs baseline: 1.2817x; 1.0911x over previous
#include <cuda_runtime.h>
#include <cstdint>

#define TS 4096
#define NH 16
#define HD 128
#define NP 512
#define BM 128
#define BN 64
#define NT 256            // 8 warps
#define NCHUNK 24
#define SCALE 0.08838834764831845f

// ---- device scratch: bf16 hi/lo planes, packed 2 consecutive elems per u32 ----
// K planes: [blk 3][h 16][j 512][dpair 64]
__device__ uint32_t g_khi[3*16*512*64];
__device__ uint32_t g_klo[3*16*512*64];
// V^T planes: [blk 3][h 16][d 128][jpair 256]
__device__ uint32_t g_vthi[3*16*128*256];
__device__ uint32_t g_vtlo[3*16*128*256];
// Q planes: [s 4096][h 16][dpair 64]
__device__ uint32_t g_qhi[4096*16*64];
__device__ uint32_t g_qlo[4096*16*64];

static __device__ __forceinline__ uint32_t s2u(const void* p){
  uint32_t a; asm("{ .reg .u64 t; cvta.to.shared.u64 t, %1; cvt.u32.u64 %0, t; }" : "=r"(a) : "l"(p)); return a;
}
static __device__ __forceinline__ uint16_t f2bf(float x){
  uint16_t r; asm("cvt.rn.bf16.f32 %0, %1;" : "=h"(r) : "f"(x)); return r;
}
static __device__ __forceinline__ float bf2f(uint16_t b){
  return __uint_as_float(((uint32_t)b) << 16);
}
// pack two floats -> bf16x2 (lo = x0, hi = x1)
static __device__ __forceinline__ uint32_t packbf(float x0, float x1){
  uint32_t r; asm("cvt.rn.bf16x2.f32 %0, %1, %2;" : "=r"(r) : "f"(x1), "f"(x0)); return r;
}
static __device__ __forceinline__ void splitpair(float x0, float x1, uint32_t& hi, uint32_t& lo){
  hi = packbf(x0, x1);
  float h0 = bf2f((uint16_t)(hi & 0xffffu));
  float h1 = bf2f((uint16_t)(hi >> 16));
  lo = packbf(x0 - h0, x1 - h1);
}
static __device__ __forceinline__ void mma_bf16(float* d, const uint32_t* a, const uint32_t* b){
  asm volatile(
    "mma.sync.aligned.m16n8k16.row.col.f32.bf16.bf16.f32 "
    "{%0,%1,%2,%3}, {%4,%5,%6,%7}, {%8,%9}, {%0,%1,%2,%3};"
    : "+f"(d[0]), "+f"(d[1]), "+f"(d[2]), "+f"(d[3])
    : "r"(a[0]), "r"(a[1]), "r"(a[2]), "r"(a[3]), "r"(b[0]), "r"(b[1]));
}
static __device__ __forceinline__ void cpa16(uint32_t dst, const void* src){
  asm volatile("cp.async.cg.shared.global [%0], [%1], 16;" :: "r"(dst), "l"(src) : "memory");
}
#define CP_COMMIT() asm volatile("cp.async.commit_group;" ::: "memory")
#define CP_WAIT0()  asm volatile("cp.async.wait_group 0;" ::: "memory")

// ================= pre-pass kernels =================
// P1: K blocks -> khi/klo  (one thread per output dpair, coalesced both sides)
__global__ void prep_k(const float* __restrict__ k, const float* __restrict__ rk){
  int g = blockIdx.x * blockDim.x + threadIdx.x;       // 3*16*512*64
  int dp = g & 63; int r = g >> 6;
  int j = r & 511; r >>= 9;
  int h = r & 15;  int blk = r >> 4;
  const float* src = (blk == 0)
    ? (k  + ((size_t)j*NH + h)*HD + dp*2)
    : (rk + (((size_t)(blk-1)*NP + j)*NH + h)*HD + dp*2);
  float2 x = *(const float2*)src;
  uint32_t hi, lo; splitpair(x.x, x.y, hi, lo);
  g_khi[g] = hi; g_klo[g] = lo;
}
// P3: Q -> qhi/qlo
__global__ void prep_q(const float* __restrict__ q){
  int g = blockIdx.x * blockDim.x + threadIdx.x;       // 4096*16*64
  float2 x = *(const float2*)(q + (size_t)g*2);
  uint32_t hi, lo; splitpair(x.x, x.y, hi, lo);
  g_qhi[g] = hi; g_qlo[g] = lo;
}
// P2: V -> vthi/vtlo transposed, via smem tile (64 j x 128 d per block)
__global__ void prep_v(const float* __restrict__ v, const float* __restrict__ rv){
  __shared__ uint16_t shi[128][66];
  __shared__ uint16_t slo[128][66];
  int jt  = blockIdx.x;          // 0..7  (64-j tile)
  int h   = blockIdx.y;
  int blk = blockIdx.z;
  int tid = threadIdx.x;
  const float* src = (blk == 0) ? v : (rv + (size_t)(blk-1)*NP*NH*HD);
  // load 64 x 128 f32, split, store transposed in smem
  #pragma unroll
  for (int i = 0; i < 8; i++){
    int f = i*256 + tid;                // float4 index
    int j = f >> 5; int d0 = (f & 31) << 2;
    float4 x = *(const float4*)(src + ((size_t)(jt*64 + j)*NH + h)*HD + d0);
    uint16_t h0 = f2bf(x.x), h1 = f2bf(x.y), h2 = f2bf(x.z), h3 = f2bf(x.w);
    shi[d0+0][j] = h0; shi[d0+1][j] = h1; shi[d0+2][j] = h2; shi[d0+3][j] = h3;
    slo[d0+0][j] = f2bf(x.x - bf2f(h0));
    slo[d0+1][j] = f2bf(x.y - bf2f(h1));
    slo[d0+2][j] = f2bf(x.z - bf2f(h2));
    slo[d0+3][j] = f2bf(x.w - bf2f(h3));
  }
  __syncthreads();
  // write packed rows: [d][jpair]
  size_t base = ((size_t)(blk*NH + h)*128)*256 + jt*32;
  #pragma unroll
  for (int i = 0; i < 16; i++){
    int u = i*256 + tid;                // 128*32
    int d = u >> 5; int jp = u & 31;
    g_vthi[base + (size_t)d*256 + jp] = ((uint32_t)shi[d][jp*2+1] << 16) | shi[d][jp*2];
    g_vtlo[base + (size_t)d*256 + jp] = ((uint32_t)slo[d][jp*2+1] << 16) | slo[d][jp*2];
  }
}

// ================= main kernel =================
// smem (u32 units): Qhi[128][68], Qlo[128][68], Khi[2][64][68], Klo[2][64][68],
//                   Vthi[2][128][36], Vtlo[2][128][36]
#define QH_OFF  0
#define QL_OFF  (QH_OFF + 128*68)
#define KH_OFF  (QL_OFF + 128*68)          // + buf*64*68
#define KL_OFF  (KH_OFF + 2*64*68)
#define VH_OFF  (KL_OFF + 2*64*68)         // + buf*128*36
#define VL_OFF  (VH_OFF + 2*128*36)
#define SMEM_U32 (VL_OFF + 2*128*36)       // 53248 u32 = 212992 B

static __device__ __forceinline__ void load_chunk(uint32_t sb, int t, int h, int buf, int tid){
  int blk = (t < 8) ? 0 : (1 + ((t - 8) >> 3));
  int j0  = ((t < 8) ? t : ((t - 8) & 7)) * BN;
  const uint32_t* kh = g_khi + ((size_t)(blk*NH + h)*512 + j0)*64;
  const uint32_t* kl = g_klo + ((size_t)(blk*NH + h)*512 + j0)*64;
  const uint32_t* vh = g_vthi + ((size_t)(blk*NH + h)*128)*256 + (j0 >> 1);
  const uint32_t* vl = g_vtlo + ((size_t)(blk*NH + h)*128)*256 + (j0 >> 1);
  uint32_t kdh = sb + (KH_OFF + buf*64*68)*4u;
  uint32_t kdl = sb + (KL_OFF + buf*64*68)*4u;
  uint32_t vdh = sb + (VH_OFF + buf*128*36)*4u;
  uint32_t vdl = sb + (VL_OFF + buf*128*36)*4u;
  #pragma unroll
  for (int i = 0; i < 4; i++){
    int f = i*NT + tid;                    // 1024 cpa16 per plane
    int row = f >> 4, seg = f & 15;        // K: 64 rows x 16 segs
    cpa16(kdh + (uint32_t)(row*68 + seg*4)*4u, kh + (size_t)row*64 + seg*4);
    cpa16(kdl + (uint32_t)(row*68 + seg*4)*4u, kl + (size_t)row*64 + seg*4);
    int vrow = f >> 3, vseg = f & 7;       // V: 128 rows x 8 segs
    cpa16(vdh + (uint32_t)(vrow*36 + vseg*4)*4u, vh + (size_t)vrow*256 + vseg*4);
    cpa16(vdl + (uint32_t)(vrow*36 + vseg*4)*4u, vl + (size_t)vrow*256 + vseg*4);
  }
}

__global__ __launch_bounds__(NT, 1)
void regional_attn_main(const int* __restrict__ masks, float* __restrict__ out)
{
  extern __shared__ uint32_t smu[];
  const uint32_t sb = s2u(smu);
  const int tid  = threadIdx.x;
  const int lane = tid & 31;
  const int wid  = tid >> 5;
  const int quad = lane >> 2;
  const int qt   = lane & 3;
  const int h = blockIdx.y;
  const int sBase = blockIdx.x * BM;

  // prologue: Q planes + chunk 0
  {
    const uint32_t* qh = g_qhi + ((size_t)sBase*NH + h)*64;
    const uint32_t* ql = g_qlo + ((size_t)sBase*NH + h)*64;
    #pragma unroll
    for (int i = 0; i < 8; i++){
      int f = i*NT + tid;                  // 2048 cpa16 per plane
      int row = f >> 4, seg = f & 15;
      cpa16(sb + (uint32_t)(QH_OFF + row*68 + seg*4)*4u, qh + (size_t)row*NH*64 + seg*4);
      cpa16(sb + (uint32_t)(QL_OFF + row*68 + seg*4)*4u, ql + (size_t)row*NH*64 + seg*4);
    }
  }
  load_chunk(sb, 0, h, 0, tid);
  CP_COMMIT();

  const int s0 = sBase + wid*16 + quad;
  const int s1 = s0 + 8;
  const int m0r0 = (masks[s0]      != 0), m0r1 = (masks[s1]      != 0);
  const int m1r0 = (masks[TS + s0] != 0), m1r1 = (masks[TS + s1] != 0);

  float oB[16][4], oR[16][4];
  #pragma unroll
  for (int n = 0; n < 16; n++)
    #pragma unroll
    for (int e = 0; e < 4; e++){ oB[n][e] = 0.f; oR[n][e] = 0.f; }
  float lB0 = 0.f, lB1 = 0.f, lR0 = 0.f, lR1 = 0.f;

  const uint32_t* Qh = smu + QH_OFF + (wid*16 + quad)*68;
  const uint32_t* Ql = smu + QL_OFF + (wid*16 + quad)*68;

  for (int t = 0; t < NCHUNK; t++){
    CP_WAIT0();
    __syncthreads();
    if (t + 1 < NCHUNK){
      load_chunk(sb, t+1, h, (t+1)&1, tid);
      CP_COMMIT();
    }

    const uint32_t* Kh = smu + KH_OFF + (t&1)*64*68 + quad*68 + qt;
    const uint32_t* Kl = smu + KL_OFF + (t&1)*64*68 + quad*68 + qt;
    const uint32_t* Vh = smu + VH_OFF + (t&1)*128*36 + quad*36 + qt;
    const uint32_t* Vl = smu + VL_OFF + (t&1)*128*36 + quad*36 + qt;

    // ---- QK^T (3-term bf16): S = Qh*Kh + Qh*Kl + Ql*Kh
    float sf[8][4];
    #pragma unroll
    for (int n = 0; n < 8; n++)
      #pragma unroll
      for (int e = 0; e < 4; e++) sf[n][e] = 0.f;

    #pragma unroll
    for (int ks = 0; ks < 8; ks++){
      uint32_t ah[4], al[4];
      ah[0] = Qh[ks*8 + qt];          al[0] = Ql[ks*8 + qt];
      ah[1] = Qh[8*68 + ks*8 + qt];   al[1] = Ql[8*68 + ks*8 + qt];
      ah[2] = Qh[ks*8 + qt + 4];      al[2] = Ql[ks*8 + qt + 4];
      ah[3] = Qh[8*68 + ks*8 + qt+4]; al[3] = Ql[8*68 + ks*8 + qt + 4];
      #pragma unroll
      for (int n = 0; n < 8; n++){
        uint32_t bh[2], bl[2];
        bh[0] = Kh[n*8*68 + ks*8];     bh[1] = Kh[n*8*68 + ks*8 + 4];
        bl[0] = Kl[n*8*68 + ks*8];     bl[1] = Kl[n*8*68 + ks*8 + 4];
        mma_bf16(sf[n], ah, bh);
        mma_bf16(sf[n], ah, bl);
        mma_bf16(sf[n], al, bh);
      }
    }

    // ---- softmax numerators + bf16 hi/lo split of P (no shuffles needed)
    const int a0 = (t < 8) ? 1 : ((t < 16) ? m0r0 : m1r0);
    const int a1 = (t < 8) ? 1 : ((t < 16) ? m0r1 : m1r1);
    uint32_t pHa[8], pHb[8], pLa[8], pLb[8];
    float su0 = 0.f, su1 = 0.f;
    #pragma unroll
    for (int n = 0; n < 8; n++){
      float p0 = a0 ? __expf(sf[n][0]*SCALE) : 0.f;
      float p1 = a0 ? __expf(sf[n][1]*SCALE) : 0.f;
      float p2 = a1 ? __expf(sf[n][2]*SCALE) : 0.f;
      float p3 = a1 ? __expf(sf[n][3]*SCALE) : 0.f;
      su0 += p0 + p1; su1 += p2 + p3;
      splitpair(p0, p1, pHa[n], pLa[n]);
      splitpair(p2, p3, pHb[n], pLb[n]);
    }
    if (t < 8){ lB0 += su0; lB1 += su1; } else { lR0 += su0; lR1 += su1; }

    // ---- P@V (3-term bf16): O += Ph*Vh + Ph*Vl + Pl*Vh
    float (*o)[4] = (t < 8) ? oB : oR;
    #pragma unroll
    for (int s = 0; s < 4; s++){
      uint32_t ph[4] = { pHa[2*s], pHb[2*s], pHa[2*s+1], pHb[2*s+1] };
      uint32_t pl[4] = { pLa[2*s], pLb[2*s], pLa[2*s+1], pLb[2*s+1] };
      #pragma unroll
      for (int n = 0; n < 16; n++){
        uint32_t bh[2], bl[2];
        bh[0] = Vh[n*8*36 + s*8];     bh[1] = Vh[n*8*36 + s*8 + 4];
        bl[0] = Vl[n*8*36 + s*8];     bl[1] = Vl[n*8*36 + s*8 + 4];
        mma_bf16(o[n], ph, bh);
        mma_bf16(o[n], ph, bl);
        mma_bf16(o[n], pl, bh);
      }
    }
  }

  // ---- epilogue
  const unsigned FULL = 0xffffffffu;
  lB0 += __shfl_xor_sync(FULL, lB0, 1, 4); lB0 += __shfl_xor_sync(FULL, lB0, 2, 4);
  lB1 += __shfl_xor_sync(FULL, lB1, 1, 4); lB1 += __shfl_xor_sync(FULL, lB1, 2, 4);
  lR0 += __shfl_xor_sync(FULL, lR0, 1, 4); lR0 += __shfl_xor_sync(FULL, lR0, 2, 4);
  lR1 += __shfl_xor_sync(FULL, lR1, 1, 4); lR1 += __shfl_xor_sync(FULL, lR1, 2, 4);

  const int anyr0 = m0r0 | m1r0;
  const int anyr1 = m0r1 | m1r1;
  const float ib0 = 1.f / lB0, ib1 = 1.f / lB1;
  const float ir0 = anyr0 ? 1.f / lR0 : 0.f;
  const float ir1 = anyr1 ? 1.f / lR1 : 0.f;

  float* o0p = out + (size_t)s0*(size_t)(NH*HD) + (size_t)h*HD + 2*qt;
  float* o1p = out + (size_t)s1*(size_t)(NH*HD) + (size_t)h*HD + 2*qt;
  #pragma unroll
  for (int n = 0; n < 16; n++){
    float b0 = oB[n][0]*ib0, b1 = oB[n][1]*ib0;
    float b2 = oB[n][2]*ib1, b3 = oB[n][3]*ib1;
    float r0 = anyr0 ? oR[n][0]*ir0 : b0;
    float r1 = anyr0 ? oR[n][1]*ir0 : b1;
    float r2 = anyr1 ? oR[n][2]*ir1 : b2;
    float r3 = anyr1 ? oR[n][3]*ir1 : b3;
    *(float2*)(o0p + n*8) = make_float2(0.5f*(b0+r0), 0.5f*(b1+r1));
    *(float2*)(o1p + n*8) = make_float2(0.5f*(b2+r2), 0.5f*(b3+r3));
  }
}

extern "C" void kernel_launch(void* const* d_in, const int* in_sizes, int n_in,
                              void* d_out, int out_size)
{
  const float* q     = (const float*)d_in[0];
  const float* k     = (const float*)d_in[1];
  const float* v     = (const float*)d_in[2];
  const float* rk    = (const float*)d_in[3];
  const float* rv    = (const float*)d_in[4];
  const int*   masks = (const int*)d_in[5];
  float* out = (float*)d_out;

  // pre-pass: split to bf16 hi/lo planes
  prep_k<<<3*16*512*64/256, 256>>>(k, rk);
  prep_q<<<4096*16*64/256, 256>>>(q);
  { dim3 g(8, 16, 3); prep_v<<<g, 256>>>(v, rv); }

  const int smem = SMEM_U32 * 4;
  cudaFuncSetAttribute(regional_attn_main,
                       cudaFuncAttributeMaxDynamicSharedMemorySize, smem);
  dim3 grid(TS / BM, NH);   // (32, 16)
  regional_attn_main<<<grid, NT, smem>>>(masks, out);
}

// round 8
// speedup vs baseline: 3.7394x; 2.9176x over previous
#include <cuda_runtime.h>
#include <cstdint>

#define TS 4096
#define NH 16
#define HD 128
#define NP 512
#define BM 128
#define BN 64
#define NT 256            // 8 warps
#define SCALE 0.08838834764831845f

// ---- device scratch: bf16 hi/lo planes, packed 2 consecutive elems per u32 ----
__device__ uint32_t g_khi[3*16*512*64];
__device__ uint32_t g_klo[3*16*512*64];
__device__ uint32_t g_vthi[3*16*128*256];
__device__ uint32_t g_vtlo[3*16*128*256];
__device__ uint32_t g_qhi[4096*16*64];
__device__ uint32_t g_qlo[4096*16*64];

static __device__ __forceinline__ uint32_t s2u(const void* p){
  uint32_t a; asm("{ .reg .u64 t; cvta.to.shared.u64 t, %1; cvt.u32.u64 %0, t; }" : "=r"(a) : "l"(p)); return a;
}
static __device__ __forceinline__ uint16_t f2bf(float x){
  uint16_t r; asm("cvt.rn.bf16.f32 %0, %1;" : "=h"(r) : "f"(x)); return r;
}
static __device__ __forceinline__ float bf2f(uint16_t b){
  return __uint_as_float(((uint32_t)b) << 16);
}
static __device__ __forceinline__ uint32_t packbf(float x0, float x1){
  uint32_t r; asm("cvt.rn.bf16x2.f32 %0, %1, %2;" : "=r"(r) : "f"(x1), "f"(x0)); return r;
}
static __device__ __forceinline__ void splitpair(float x0, float x1, uint32_t& hi, uint32_t& lo){
  hi = packbf(x0, x1);
  float h0 = bf2f((uint16_t)(hi & 0xffffu));
  float h1 = bf2f((uint16_t)(hi >> 16));
  lo = packbf(x0 - h0, x1 - h1);
}
static __device__ __forceinline__ void mma_bf16(float* d, const uint32_t* a, const uint32_t* b){
  asm volatile(
    "mma.sync.aligned.m16n8k16.row.col.f32.bf16.bf16.f32 "
    "{%0,%1,%2,%3}, {%4,%5,%6,%7}, {%8,%9}, {%0,%1,%2,%3};"
    : "+f"(d[0]), "+f"(d[1]), "+f"(d[2]), "+f"(d[3])
    : "r"(a[0]), "r"(a[1]), "r"(a[2]), "r"(a[3]), "r"(b[0]), "r"(b[1]));
}
static __device__ __forceinline__ void cpa16(uint32_t dst, const void* src){
  asm volatile("cp.async.cg.shared.global [%0], [%1], 16;" :: "r"(dst), "l"(src) : "memory");
}
#define CP_COMMIT() asm volatile("cp.async.commit_group;" ::: "memory")
#define CP_WAIT0()  asm volatile("cp.async.wait_group 0;" ::: "memory")

// ================= pre-pass kernels (unchanged from R7, verified) =================
__global__ void prep_k(const float* __restrict__ k, const float* __restrict__ rk){
  int g = blockIdx.x * blockDim.x + threadIdx.x;
  int dp = g & 63; int r = g >> 6;
  int j = r & 511; r >>= 9;
  int h = r & 15;  int blk = r >> 4;
  const float* src = (blk == 0)
    ? (k  + ((size_t)j*NH + h)*HD + dp*2)
    : (rk + (((size_t)(blk-1)*NP + j)*NH + h)*HD + dp*2);
  float2 x = *(const float2*)src;
  uint32_t hi, lo; splitpair(x.x, x.y, hi, lo);
  g_khi[g] = hi; g_klo[g] = lo;
}
__global__ void prep_q(const float* __restrict__ q){
  int g = blockIdx.x * blockDim.x + threadIdx.x;
  float2 x = *(const float2*)(q + (size_t)g*2);
  uint32_t hi, lo; splitpair(x.x, x.y, hi, lo);
  g_qhi[g] = hi; g_qlo[g] = lo;
}
__global__ void prep_v(const float* __restrict__ v, const float* __restrict__ rv){
  __shared__ uint16_t shi[128][66];
  __shared__ uint16_t slo[128][66];
  int jt  = blockIdx.x;
  int h   = blockIdx.y;
  int blk = blockIdx.z;
  int tid = threadIdx.x;
  const float* src = (blk == 0) ? v : (rv + (size_t)(blk-1)*NP*NH*HD);
  #pragma unroll
  for (int i = 0; i < 8; i++){
    int f = i*256 + tid;
    int j = f >> 5; int d0 = (f & 31) << 2;
    float4 x = *(const float4*)(src + ((size_t)(jt*64 + j)*NH + h)*HD + d0);
    uint16_t h0 = f2bf(x.x), h1 = f2bf(x.y), h2 = f2bf(x.z), h3 = f2bf(x.w);
    shi[d0+0][j] = h0; shi[d0+1][j] = h1; shi[d0+2][j] = h2; shi[d0+3][j] = h3;
    slo[d0+0][j] = f2bf(x.x - bf2f(h0));
    slo[d0+1][j] = f2bf(x.y - bf2f(h1));
    slo[d0+2][j] = f2bf(x.z - bf2f(h2));
    slo[d0+3][j] = f2bf(x.w - bf2f(h3));
  }
  __syncthreads();
  size_t base = ((size_t)(blk*NH + h)*128)*256 + jt*32;
  #pragma unroll
  for (int i = 0; i < 16; i++){
    int u = i*256 + tid;
    int d = u >> 5; int jp = u & 31;
    g_vthi[base + (size_t)d*256 + jp] = ((uint32_t)shi[d][jp*2+1] << 16) | shi[d][jp*2];
    g_vtlo[base + (size_t)d*256 + jp] = ((uint32_t)slo[d][jp*2+1] << 16) | slo[d][jp*2];
  }
}

// ================= main kernel =================
#define QH_OFF  0
#define QL_OFF  (QH_OFF + 128*68)
#define KH_OFF  (QL_OFF + 128*68)
#define KL_OFF  (KH_OFF + 2*64*68)
#define VH_OFF  (KL_OFF + 2*64*68)
#define VL_OFF  (VH_OFF + 2*128*36)
#define SMEM_U32 (VL_OFF + 2*128*36)       // 53248 u32 = 212992 B

static __device__ __forceinline__ void load_chunk(uint32_t sb, int t, int h, int buf, int tid){
  int blk = (t < 8) ? 0 : (1 + ((t - 8) >> 3));
  int j0  = ((t < 8) ? t : ((t - 8) & 7)) * BN;
  const uint32_t* kh = g_khi + ((size_t)(blk*NH + h)*512 + j0)*64;
  const uint32_t* kl = g_klo + ((size_t)(blk*NH + h)*512 + j0)*64;
  const uint32_t* vh = g_vthi + ((size_t)(blk*NH + h)*128)*256 + (j0 >> 1);
  const uint32_t* vl = g_vtlo + ((size_t)(blk*NH + h)*128)*256 + (j0 >> 1);
  uint32_t kdh = sb + (KH_OFF + buf*64*68)*4u;
  uint32_t kdl = sb + (KL_OFF + buf*64*68)*4u;
  uint32_t vdh = sb + (VH_OFF + buf*128*36)*4u;
  uint32_t vdl = sb + (VL_OFF + buf*128*36)*4u;
  #pragma unroll
  for (int i = 0; i < 4; i++){
    int f = i*NT + tid;
    int row = f >> 4, seg = f & 15;
    cpa16(kdh + (uint32_t)(row*68 + seg*4)*4u, kh + (size_t)row*64 + seg*4);
    cpa16(kdl + (uint32_t)(row*68 + seg*4)*4u, kl + (size_t)row*64 + seg*4);
    int vrow = f >> 3, vseg = f & 7;
    cpa16(vdh + (uint32_t)(vrow*36 + vseg*4)*4u, vh + (size_t)vrow*256 + vseg*4);
    cpa16(vdl + (uint32_t)(vrow*36 + vseg*4)*4u, vl + (size_t)vrow*256 + vseg*4);
  }
}

// One 64-key chunk: QK (3-term bf16) -> exp -> PV (3-term bf16) into o (single array,
// compile-time indices only -> stays in registers).
static __device__ __forceinline__ void do_chunk(
    const uint32_t* __restrict__ smu, uint32_t sb, int t, int nchunk_end, int h, int tid,
    int quad, int qt, const uint32_t* __restrict__ Qh, const uint32_t* __restrict__ Ql,
    float (&o)[16][4], int a0, int a1, float& su0t, float& su1t)
{
  CP_WAIT0();
  __syncthreads();
  if (t + 1 < nchunk_end){
    load_chunk(sb, t+1, h, (t+1)&1, tid);
    CP_COMMIT();
  }

  const uint32_t* Kh = smu + KH_OFF + (t&1)*64*68 + quad*68 + qt;
  const uint32_t* Kl = smu + KL_OFF + (t&1)*64*68 + quad*68 + qt;
  const uint32_t* Vh = smu + VH_OFF + (t&1)*128*36 + quad*36 + qt;
  const uint32_t* Vl = smu + VL_OFF + (t&1)*128*36 + quad*36 + qt;

  float sf[8][4];
  #pragma unroll
  for (int n = 0; n < 8; n++)
    #pragma unroll
    for (int e = 0; e < 4; e++) sf[n][e] = 0.f;

  #pragma unroll
  for (int ks = 0; ks < 8; ks++){
    uint32_t ah[4], al[4];
    ah[0] = Qh[ks*8 + qt];          al[0] = Ql[ks*8 + qt];
    ah[1] = Qh[8*68 + ks*8 + qt];   al[1] = Ql[8*68 + ks*8 + qt];
    ah[2] = Qh[ks*8 + qt + 4];      al[2] = Ql[ks*8 + qt + 4];
    ah[3] = Qh[8*68 + ks*8 + qt+4]; al[3] = Ql[8*68 + ks*8 + qt + 4];
    #pragma unroll
    for (int n = 0; n < 8; n++){
      uint32_t bh[2], bl[2];
      bh[0] = Kh[n*8*68 + ks*8];     bh[1] = Kh[n*8*68 + ks*8 + 4];
      bl[0] = Kl[n*8*68 + ks*8];     bl[1] = Kl[n*8*68 + ks*8 + 4];
      mma_bf16(sf[n], ah, bh);
      mma_bf16(sf[n], ah, bl);
      mma_bf16(sf[n], al, bh);
    }
  }

  uint32_t pHa[8], pHb[8], pLa[8], pLb[8];
  float su0 = 0.f, su1 = 0.f;
  #pragma unroll
  for (int n = 0; n < 8; n++){
    float p0 = a0 ? __expf(sf[n][0]*SCALE) : 0.f;
    float p1 = a0 ? __expf(sf[n][1]*SCALE) : 0.f;
    float p2 = a1 ? __expf(sf[n][2]*SCALE) : 0.f;
    float p3 = a1 ? __expf(sf[n][3]*SCALE) : 0.f;
    su0 += p0 + p1; su1 += p2 + p3;
    splitpair(p0, p1, pHa[n], pLa[n]);
    splitpair(p2, p3, pHb[n], pLb[n]);
  }
  su0t += su0; su1t += su1;

  #pragma unroll
  for (int s = 0; s < 4; s++){
    uint32_t ph[4] = { pHa[2*s], pHb[2*s], pHa[2*s+1], pHb[2*s+1] };
    uint32_t pl[4] = { pLa[2*s], pLb[2*s], pLa[2*s+1], pLb[2*s+1] };
    #pragma unroll
    for (int n = 0; n < 16; n++){
      uint32_t bh[2], bl[2];
      bh[0] = Vh[n*8*36 + s*8];     bh[1] = Vh[n*8*36 + s*8 + 4];
      bl[0] = Vl[n*8*36 + s*8];     bl[1] = Vl[n*8*36 + s*8 + 4];
      mma_bf16(o[n], ph, bh);
      mma_bf16(o[n], ph, bl);
      mma_bf16(o[n], pl, bh);
    }
  }
}

__global__ __launch_bounds__(NT, 1)
void regional_attn_main(const int* __restrict__ masks, float* __restrict__ out)
{
  extern __shared__ uint32_t smu[];
  const uint32_t sb = s2u(smu);
  const int tid  = threadIdx.x;
  const int lane = tid & 31;
  const int wid  = tid >> 5;
  const int quad = lane >> 2;
  const int qt   = lane & 3;
  const int h = blockIdx.y;
  const int sBase = blockIdx.x * BM;

  {
    const uint32_t* qh = g_qhi + ((size_t)sBase*NH + h)*64;
    const uint32_t* ql = g_qlo + ((size_t)sBase*NH + h)*64;
    #pragma unroll
    for (int i = 0; i < 8; i++){
      int f = i*NT + tid;
      int row = f >> 4, seg = f & 15;
      cpa16(sb + (uint32_t)(QH_OFF + row*68 + seg*4)*4u, qh + (size_t)row*NH*64 + seg*4);
      cpa16(sb + (uint32_t)(QL_OFF + row*68 + seg*4)*4u, ql + (size_t)row*NH*64 + seg*4);
    }
  }
  load_chunk(sb, 0, h, 0, tid);
  CP_COMMIT();

  const int s0 = sBase + wid*16 + quad;
  const int s1 = s0 + 8;
  const int m0r0 = (masks[s0]      != 0), m0r1 = (masks[s1]      != 0);
  const int m1r0 = (masks[TS + s0] != 0), m1r1 = (masks[TS + s1] != 0);
  const int anyr0 = m0r0 | m1r0;
  const int anyr1 = m0r1 | m1r1;

  const uint32_t* Qh = smu + QH_OFF + (wid*16 + quad)*68;
  const uint32_t* Ql = smu + QL_OFF + (wid*16 + quad)*68;
  const unsigned FULL = 0xffffffffu;

  float o[16][4];
  #pragma unroll
  for (int n = 0; n < 16; n++)
    #pragma unroll
    for (int e = 0; e < 4; e++) o[n][e] = 0.f;

  float* o0p = out + (size_t)s0*(size_t)(NH*HD) + (size_t)h*HD + 2*qt;
  float* o1p = out + (size_t)s1*(size_t)(NH*HD) + (size_t)h*HD + 2*qt;

  // ---- base pass (chunks 0..7): always active
  {
    float l0 = 0.f, l1 = 0.f;
    #pragma unroll 1
    for (int t = 0; t < 8; t++)
      do_chunk(smu, sb, t, 24, h, tid, quad, qt, Qh, Ql, o, 1, 1, l0, l1);

    l0 += __shfl_xor_sync(FULL, l0, 1, 4); l0 += __shfl_xor_sync(FULL, l0, 2, 4);
    l1 += __shfl_xor_sync(FULL, l1, 1, 4); l1 += __shfl_xor_sync(FULL, l1, 2, 4);
    // stage-1 epilogue: out = oB/lB * (anyr ? 0.5 : 1.0)
    const float w0 = (anyr0 ? 0.5f : 1.0f) / l0;
    const float w1 = (anyr1 ? 0.5f : 1.0f) / l1;
    #pragma unroll
    for (int n = 0; n < 16; n++){
      *(float2*)(o0p + n*8) = make_float2(o[n][0]*w0, o[n][1]*w0);
      *(float2*)(o1p + n*8) = make_float2(o[n][2]*w1, o[n][3]*w1);
      o[n][0] = 0.f; o[n][1] = 0.f; o[n][2] = 0.f; o[n][3] = 0.f;
    }
  }

  // ---- regional pass (chunks 8..23): per-query gated
  {
    float l0 = 0.f, l1 = 0.f;
    #pragma unroll 1
    for (int t = 8; t < 16; t++)
      do_chunk(smu, sb, t, 24, h, tid, quad, qt, Qh, Ql, o, m0r0, m0r1, l0, l1);
    #pragma unroll 1
    for (int t = 16; t < 24; t++)
      do_chunk(smu, sb, t, 24, h, tid, quad, qt, Qh, Ql, o, m1r0, m1r1, l0, l1);

    l0 += __shfl_xor_sync(FULL, l0, 1, 4); l0 += __shfl_xor_sync(FULL, l0, 2, 4);
    l1 += __shfl_xor_sync(FULL, l1, 1, 4); l1 += __shfl_xor_sync(FULL, l1, 2, 4);
    // stage-2 epilogue: out += 0.5 * oR/lR  (zero contribution when no region)
    const float w0 = anyr0 ? (0.5f / l0) : 0.f;
    const float w1 = anyr1 ? (0.5f / l1) : 0.f;
    #pragma unroll
    for (int n = 0; n < 16; n++){
      float2 a = *(const float2*)(o0p + n*8);
      float2 b = *(const float2*)(o1p + n*8);
      a.x += o[n][0]*w0; a.y += o[n][1]*w0;
      b.x += o[n][2]*w1; b.y += o[n][3]*w1;
      *(float2*)(o0p + n*8) = a;
      *(float2*)(o1p + n*8) = b;
    }
  }
}

extern "C" void kernel_launch(void* const* d_in, const int* in_sizes, int n_in,
                              void* d_out, int out_size)
{
  const float* q     = (const float*)d_in[0];
  const float* k     = (const float*)d_in[1];
  const float* v     = (const float*)d_in[2];
  const float* rk    = (const float*)d_in[3];
  const float* rv    = (const float*)d_in[4];
  const int*   masks = (const int*)d_in[5];
  float* out = (float*)d_out;

  prep_k<<<3*16*512*64/256, 256>>>(k, rk);
  prep_q<<<4096*16*64/256, 256>>>(q);
  { dim3 g(8, 16, 3); prep_v<<<g, 256>>>(v, rv); }

  const int smem = SMEM_U32 * 4;
  cudaFuncSetAttribute(regional_attn_main,
                       cudaFuncAttributeMaxDynamicSharedMemorySize, smem);
  dim3 grid(TS / BM, NH);   // (32, 16)
  regional_attn_main<<<grid, NT, smem>>>(masks, out);
}